// round 1
// baseline (speedup 1.0000x reference)
#include <cuda_runtime.h>

#define S_MAX 200000
#define N_MAX 250000
#define LB 64           // L == B == 64

// ---- device scratch (no allocations allowed) ----
__device__ float g_xT[(size_t)N_MAX * LB];    // x transposed [N,64]
__device__ float g_yT[(size_t)S_MAX * LB];    // y transposed [S,64]
__device__ float g_outT[(size_t)N_MAX * LB];  // out accumulator [N,64]
__device__ float g_z[LB * LB];                // z stored l-major: z[l][b]
__device__ int   g_cm[S_MAX];                 // # added new nodes per master
__device__ int   g_cnt[N_MAX];                // # masters mapping to n
__device__ float g_bdacc[N_MAX];              // segment sum of bd_m
__device__ unsigned char g_added[N_MAX];

// ---------------- clear ----------------
__global__ void k_clear(int S, int N) {
    int i = blockIdx.x * blockDim.x + threadIdx.x;
    int tot4 = N * 16;  // N*64 floats / 4
    if (i < tot4) ((float4*)g_outT)[i] = make_float4(0.f, 0.f, 0.f, 0.f);
    if (i < N) { g_cnt[i] = 0; g_bdacc[i] = 0.f; }
    if (i < S) g_cm[i] = 0;
}

__global__ void k_zbias(const float* __restrict__ be) {
    int i = threadIdx.x + blockIdx.x * blockDim.x;
    if (i < LB * LB) g_z[i] = be[i >> 6];     // z[l][b] = be[l]
}

// ---------------- added flags + c_m ----------------
__global__ void k_added(const int* __restrict__ nn_n, const int* __restrict__ nn_m, int N) {
    int n = blockIdx.x * blockDim.x + threadIdx.x;
    if (n < N) {
        int m = nn_n[n];
        int a = (nn_m[m] != n) ? 1 : 0;
        g_added[n] = (unsigned char)a;
        if (a) atomicAdd(&g_cm[m], 1);
    }
}

// ---------------- cnt + bd segment sums ----------------
__global__ void k_mstats(const int* __restrict__ nn_m, const float* __restrict__ bd, int S) {
    int m = blockIdx.x * blockDim.x + threadIdx.x;
    if (m < S) {
        int nm = nn_m[m];
        atomicAdd(&g_cnt[nm], 1);
        atomicAdd(&g_bdacc[nm], bd[m]);
    }
}

// ---------------- x transpose [64,N] -> [N,64] ----------------
__global__ void k_xT(const float* __restrict__ x, int N) {
    __shared__ float tile[32][33];
    int n0 = blockIdx.x * 32;
    int b0 = blockIdx.y * 32;
    int tx = threadIdx.x, ty = threadIdx.y;   // 32 x 8
    #pragma unroll
    for (int i = 0; i < 32; i += 8) {
        int n = n0 + tx;
        tile[ty + i][tx] = (n < N) ? x[(size_t)(b0 + ty + i) * N + n] : 0.f;
    }
    __syncthreads();
    #pragma unroll
    for (int i = 0; i < 32; i += 8) {
        int n = n0 + ty + i;
        if (n < N) g_xT[(size_t)n * LB + b0 + tx] = tile[tx][ty + i];
    }
}

// ---------------- z GEMM: z[l][b] += sum over K=S+N rank-1 updates ----------------
#define ZCHUNK 1024
#define ZG 8

__global__ void __launch_bounds__(256) k_z(const float* __restrict__ We,
                                           const int* __restrict__ nn_n,
                                           const int* __restrict__ nn_m,
                                           int S, int N) {
    __shared__ float sx[ZG][64];
    __shared__ float sw[ZG][64];
    int tid = threadIdx.x;
    int tx = tid & 15, ty = tid >> 4;        // thread -> (l-group, b-group)
    int r = tid >> 5;                        // staging row 0..7
    int c = (tid & 31) * 2;                  // staging col (2 floats)
    float acc[4][4];
    #pragma unroll
    for (int i = 0; i < 4; i++)
        #pragma unroll
        for (int j = 0; j < 4; j++) acc[i][j] = 0.f;

    int Ktot = S + N;
    int k0 = blockIdx.x * ZCHUNK;

    for (int kk = 0; kk < ZCHUNK; kk += ZG) {
        int k = k0 + kk + r;
        const float* px = 0;
        const float* pw = 0;
        float scale = 0.f;
        if (k < Ktot) {
            if (k < S) {
                scale = 1.0f / (float)(g_cm[k] + 1);
                pw = We + (size_t)k * 64;
                px = g_xT + (size_t)nn_m[k] * 64;
            } else {
                int n = k - S;
                if (g_added[n]) {
                    int m = nn_n[n];
                    scale = 1.0f / (float)(g_cm[m] + 1);
                    pw = We + (size_t)m * 64;
                    px = g_xT + (size_t)n * 64;
                }
            }
        }
        __syncthreads();
        if (pw) {
            float2 w2 = *(const float2*)(pw + c);
            float2 x2 = *(const float2*)(px + c);
            sw[r][c] = w2.x * scale; sw[r][c + 1] = w2.y * scale;
            sx[r][c] = x2.x;         sx[r][c + 1] = x2.y;
        } else {
            sw[r][c] = 0.f; sw[r][c + 1] = 0.f;
            sx[r][c] = 0.f; sx[r][c + 1] = 0.f;
        }
        __syncthreads();
        #pragma unroll
        for (int g = 0; g < ZG; g++) {
            float4 xv = *(const float4*)&sx[g][ty * 4];
            float4 wv = *(const float4*)&sw[g][tx * 4];
            acc[0][0] += xv.x * wv.x; acc[0][1] += xv.x * wv.y; acc[0][2] += xv.x * wv.z; acc[0][3] += xv.x * wv.w;
            acc[1][0] += xv.y * wv.x; acc[1][1] += xv.y * wv.y; acc[1][2] += xv.y * wv.z; acc[1][3] += xv.y * wv.w;
            acc[2][0] += xv.z * wv.x; acc[2][1] += xv.z * wv.y; acc[2][2] += xv.z * wv.z; acc[2][3] += xv.z * wv.w;
            acc[3][0] += xv.w * wv.x; acc[3][1] += xv.w * wv.y; acc[3][2] += xv.w * wv.z; acc[3][3] += xv.w * wv.w;
        }
    }
    #pragma unroll
    for (int i = 0; i < 4; i++)
        #pragma unroll
        for (int j = 0; j < 4; j++)
            atomicAdd(&g_z[(tx * 4 + j) * 64 + (ty * 4 + i)], acc[i][j]);
}

// ---------------- y = z @ Wd (per 128-column tile) + scatter into out_T ----------------
__global__ void __launch_bounds__(256) k_y1(const float* __restrict__ Wd,
                                            const int* __restrict__ nn_m, int S) {
    __shared__ float sbuf[128 * 68];   // first 4096 floats: z[l][b]; reused as y tile [128][68]
    int tid = threadIdx.x;
    int m0 = blockIdx.x * 128;
    for (int i = tid; i < 4096; i += 256) sbuf[i] = g_z[i];
    __syncthreads();

    int tx = tid & 31, ty = tid >> 5;
    int mbase = m0 + tx * 4;
    bool valid = (mbase + 4) <= S;     // S % 4 == 0, tiles of 4 all-or-nothing

    float acc[8][4];
    #pragma unroll
    for (int bi = 0; bi < 8; bi++)
        #pragma unroll
        for (int mj = 0; mj < 4; mj++) acc[bi][mj] = 0.f;

    #pragma unroll 4
    for (int l = 0; l < 64; l++) {
        float4 wv = valid ? *(const float4*)&Wd[(size_t)l * S + mbase]
                          : make_float4(0.f, 0.f, 0.f, 0.f);
        float4 z0 = *(const float4*)&sbuf[l * 64 + ty * 8];
        float4 z1 = *(const float4*)&sbuf[l * 64 + ty * 8 + 4];
        float zb[8] = {z0.x, z0.y, z0.z, z0.w, z1.x, z1.y, z1.z, z1.w};
        #pragma unroll
        for (int bi = 0; bi < 8; bi++) {
            acc[bi][0] += zb[bi] * wv.x;
            acc[bi][1] += zb[bi] * wv.y;
            acc[bi][2] += zb[bi] * wv.z;
            acc[bi][3] += zb[bi] * wv.w;
        }
    }
    __syncthreads();  // done reading z region; reuse sbuf as y tile

    #pragma unroll
    for (int bi = 0; bi < 8; bi++)
        #pragma unroll
        for (int mj = 0; mj < 4; mj++)
            sbuf[(tx * 4 + mj) * 68 + (ty * 8 + bi)] = acc[bi][mj];
    __syncthreads();

    int cr = tid >> 4;              // 0..15
    int cc = (tid & 15) * 4;        // 0..60
    for (int rr = cr; rr < 128; rr += 16) {
        int m = m0 + rr;
        if (m < S) {
            float4 v = *(const float4*)&sbuf[rr * 68 + cc];
            *(float4*)&g_yT[(size_t)m * 64 + cc] = v;
            int nm = nn_m[m];
            float* dst = &g_outT[(size_t)nm * 64 + cc];
            atomicAdd(dst + 0, v.x);
            atomicAdd(dst + 1, v.y);
            atomicAdd(dst + 2, v.z);
            atomicAdd(dst + 3, v.w);
        }
    }
}

// ---------------- finalize: add gathered added-term, scale, bias, transpose-store ----------------
__global__ void __launch_bounds__(256) k_y2(float* __restrict__ out,
                                            const float* __restrict__ bd,
                                            const int* __restrict__ nn_n, int N) {
    __shared__ float t[64][65];
    int n0 = blockIdx.x * 64;
    int tid = threadIdx.x;
    int r = tid >> 2;
    int q = (tid & 3) * 16;
    int n = n0 + r;
    if (n < N) {
        int a = g_added[n];
        int m = nn_n[n];
        float dn = (float)(g_cnt[n] + a);
        if (dn < 1.f) dn = 1.f;
        float inv = 1.0f / dn;
        float bdn = (g_bdacc[n] + (a ? bd[m] : 0.f)) * inv;
        const float* yr = g_yT + (size_t)m * 64;
        const float* oa = g_outT + (size_t)n * 64;
        #pragma unroll
        for (int j = 0; j < 16; j += 4) {
            int b = q + j;
            float4 ov = *(const float4*)&oa[b];
            if (a) {
                float4 yv = *(const float4*)&yr[b];
                ov.x += yv.x; ov.y += yv.y; ov.z += yv.z; ov.w += yv.w;
            }
            t[r][b]     = ov.x * inv + bdn;
            t[r][b + 1] = ov.y * inv + bdn;
            t[r][b + 2] = ov.z * inv + bdn;
            t[r][b + 3] = ov.w * inv + bdn;
        }
    }
    __syncthreads();
    int cidx = tid & 63;
    if (n0 + cidx < N) {
        #pragma unroll
        for (int b = tid >> 6; b < 64; b += 4)
            out[(size_t)b * N + n0 + cidx] = t[cidx][b];
    }
}

extern "C" void kernel_launch(void* const* d_in, const int* in_sizes, int n_in,
                              void* d_out, int out_size) {
    const float* We   = (const float*)d_in[0];
    const float* be   = (const float*)d_in[1];
    const float* Wd   = (const float*)d_in[2];
    const float* bd   = (const float*)d_in[3];
    const float* x    = (const float*)d_in[4];
    const int*   nn_n = (const int*)d_in[5];
    const int*   nn_m = (const int*)d_in[6];
    int S = in_sizes[3];   // bd_m has S elements
    int N = in_sizes[5];   // nn_n has N elements
    float* out = (float*)d_out;

    int clearGrid = (N * 16 + 255) / 256;
    k_clear<<<clearGrid, 256>>>(S, N);
    k_zbias<<<16, 256>>>(be);
    k_added<<<(N + 255) / 256, 256>>>(nn_n, nn_m, N);
    k_mstats<<<(S + 255) / 256, 256>>>(nn_m, bd, S);

    dim3 tb(32, 8);
    dim3 tg((N + 31) / 32, 2);
    k_xT<<<tg, tb>>>(x, N);

    int Ktot = S + N;
    k_z<<<(Ktot + ZCHUNK - 1) / ZCHUNK, 256>>>(We, nn_n, nn_m, S, N);
    k_y1<<<(S + 127) / 128, 256>>>(Wd, nn_m, S);
    k_y2<<<(N + 63) / 64, 256>>>(out, bd, nn_n, N);
}